// round 7
// baseline (speedup 1.0000x reference)
#include <cuda_runtime.h>
#include <cuda_bf16.h>
#include <cstdint>

#define BATCH 8
#define NPTS  4096
#define CFEAT 128
#define NPOINT 1024
#define NSAMPLE 32
#define COUT  256
#define CIN   131   // 3 + 128

typedef unsigned long long u64;

// ---------------- scratch (device globals; no allocation allowed) ----------------
__device__ float  g_P[BATCH * NPTS * COUT];          // 33.5 MB  per-point feature GEMM result
__device__ int    g_gidx[BATCH * NPOINT * NSAMPLE];  // ball query indices
__device__ float  g_cent[BATCH * NPOINT * 3];        // new_xyz copy for device use
__device__ float  g_scale[CIN];                      // gamma / sqrt(var+eps)
__device__ float  g_Wt[CIN * COUT];                  // W transposed
__device__ float4 g_xyz4[BATCH * NPTS];              // padded xyz for 1-LDG ballq

// ---------------- packed f32x2 helpers (bit-identical to scalar rn ops) ----------------
__device__ __forceinline__ u64 f2_add(u64 a, u64 b) {
    u64 r; asm("add.rn.f32x2 %0,%1,%2;" : "=l"(r) : "l"(a), "l"(b)); return r;
}
__device__ __forceinline__ u64 f2_mul(u64 a, u64 b) {
    u64 r; asm("mul.rn.f32x2 %0,%1,%2;" : "=l"(r) : "l"(a), "l"(b)); return r;
}
__device__ __forceinline__ u64 f2_pack(float lo, float hi) {
    u64 r; asm("mov.b64 %0,{%1,%2};" : "=l"(r) : "f"(lo), "f"(hi)); return r;
}
__device__ __forceinline__ void f2_unpack(u64 v, float& lo, float& hi) {
    asm("mov.b64 {%0,%1},%2;" : "=f"(lo), "=f"(hi) : "l"(v));
}

// ---------------- init: BN scale + W transpose ----------------
__global__ void init_kernel(const float* __restrict__ W,
                            const float* __restrict__ gamma,
                            const float* __restrict__ var) {
    int idx = blockIdx.x * blockDim.x + threadIdx.x;
    if (idx < CIN * COUT) {
        int o = idx & 255;
        int c = idx >> 8;
        g_Wt[c * COUT + o] = W[o * CIN + c];
    }
    if (idx < CIN) {
        g_scale[idx] = gamma[idx] / sqrtf(var[idx] + 1e-5f);
    }
}

// ---------------- prep: pad xyz into float4 (runs under FPS on side stream) ----------------
__global__ void __launch_bounds__(256) prep_kernel(const float* __restrict__ xyz) {
    int i = blockIdx.x * blockDim.x + threadIdx.x;   // 0..32767
    if (i < BATCH * NPTS) {
        g_xyz4[i] = make_float4(xyz[i * 3 + 0], xyz[i * 3 + 1], xyz[i * 3 + 2], 0.f);
    }
}

// ---------------- furthest point sampling (R2 exact — empirical optimum) ----------------
__global__ void __launch_bounds__(128, 1) fps_kernel(const float* __restrict__ xyz,
                                                     float* __restrict__ out_xyz) {
    const int b = blockIdx.x;
    const float* X = xyz + (size_t)b * NPTS * 3;
    const int t    = threadIdx.x;
    const int lane = t & 31;
    const int wid  = t >> 5;
    const int base = t * 32;

    u64 PX[16], PY[16], PZ[16];
    float mind[32];
#pragma unroll
    for (int i = 0; i < 16; i++) {
        int p0 = base + 2 * i;
        float x0 = X[p0 * 3 + 0], y0 = X[p0 * 3 + 1], z0 = X[p0 * 3 + 2];
        float x1 = X[p0 * 3 + 3], y1 = X[p0 * 3 + 4], z1 = X[p0 * 3 + 5];
        PX[i] = f2_pack(x0, x1);
        PY[i] = f2_pack(y0, y1);
        PZ[i] = f2_pack(z0, z1);
        mind[2 * i] = 1e10f;
        mind[2 * i + 1] = 1e10f;
    }

    __shared__ u64 s_part[2][4];

    float qx = X[0], qy = X[1], qz = X[2];
    if (t == 0) {
        size_t r = (size_t)(b * NPOINT) * 3;
        g_cent[r + 0] = qx; g_cent[r + 1] = qy; g_cent[r + 2] = qz;
        out_xyz[r + 0] = qx; out_xyz[r + 1] = qy; out_xyz[r + 2] = qz;
    }

    for (int it = 1; it < NPOINT; ++it) {
        const u64 nqx = f2_pack(-qx, -qx);
        const u64 nqy = f2_pack(-qy, -qy);
        const u64 nqz = f2_pack(-qz, -qz);

        unsigned bb = 0u;   // best mind bits (nonneg float -> bits monotonic)
        int bi = 0;
#pragma unroll
        for (int i = 0; i < 16; i++) {
            u64 dx = f2_add(PX[i], nqx);
            u64 dy = f2_add(PY[i], nqy);
            u64 dz = f2_add(PZ[i], nqz);
            u64 s  = f2_add(f2_add(f2_mul(dx, dx), f2_mul(dy, dy)), f2_mul(dz, dz));
            float s0, s1;
            f2_unpack(s, s0, s1);
            mind[2 * i]     = fminf(mind[2 * i], s0);
            mind[2 * i + 1] = fminf(mind[2 * i + 1], s1);
            unsigned m0 = __float_as_uint(mind[2 * i]);
            if (m0 > bb) { bb = m0; bi = base + 2 * i; }       // strict > keeps earliest index
            unsigned m1 = __float_as_uint(mind[2 * i + 1]);
            if (m1 > bb) { bb = m1; bi = base + 2 * i + 1; }
        }

        unsigned wmax = __reduce_max_sync(0xffffffffu, bb);
        unsigned ball = __ballot_sync(0xffffffffu, bb == wmax);
        int src = __ffs(ball) - 1;
        int wbi = __shfl_sync(0xffffffffu, bi, src);
        if (lane == 0)
            s_part[it & 1][wid] = ((u64)wmax << 32) | (unsigned)(~wbi);
        __syncthreads();

        u64 w0 = s_part[it & 1][0];
        u64 w1 = s_part[it & 1][1];
        u64 w2 = s_part[it & 1][2];
        u64 w3 = s_part[it & 1][3];
        u64 win = w0;
        if (w1 > win) win = w1;
        if (w2 > win) win = w2;
        if (w3 > win) win = w3;
        int li = (int)(~(unsigned)win);

        qx = X[li * 3 + 0]; qy = X[li * 3 + 1]; qz = X[li * 3 + 2];
        if (t == 0) {
            size_t r = (size_t)(b * NPOINT + it) * 3;
            g_cent[r + 0] = qx; g_cent[r + 1] = qy; g_cent[r + 2] = qz;
            out_xyz[r + 0] = qx; out_xyz[r + 1] = qy; out_xyz[r + 2] = qz;
        }
    }
}

// ---------------- ball query: warp per center, float4 loads ----------------
__global__ void __launch_bounds__(1024) ballq_kernel() {
    const int b    = blockIdx.x >> 5;                       // 256 blocks: 32 per batch
    const int s    = ((blockIdx.x & 31) << 5) + (threadIdx.x >> 5);
    const int lane = threadIdx.x & 31;
    const float4* X4 = g_xyz4 + (size_t)b * NPTS;

    const size_t g = (size_t)b * NPOINT + s;
    const float cx = g_cent[g * 3 + 0];
    const float cy = g_cent[g * 3 + 1];
    const float cz = g_cent[g * 3 + 2];
    int* out = g_gidx + g * NSAMPLE;

    const float R2 = (float)(0.1 * 0.1);

    int cnt = 0;
    int first = -1;
    for (int basej = 0; basej < NPTS; basej += 32) {
        int j = basej + lane;
        float4 p = X4[j];
        float dx = __fsub_rn(cx, p.x);
        float dy = __fsub_rn(cy, p.y);
        float dz = __fsub_rn(cz, p.z);
        float d2 = __fadd_rn(__fadd_rn(__fmul_rn(dx, dx), __fmul_rn(dy, dy)),
                             __fmul_rn(dz, dz));
        bool valid = d2 < R2;
        unsigned mask = __ballot_sync(0xffffffffu, valid);
        if (first < 0 && mask) first = basej + __ffs(mask) - 1;
        if (valid) {
            int pos = cnt + __popc(mask & ((1u << lane) - 1u));
            if (pos < NSAMPLE) out[pos] = j;
        }
        cnt += __popc(mask);
        if (cnt >= NSAMPLE) break;
    }
    if (lane >= cnt && lane < NSAMPLE) out[lane] = first;   // cnt>=1 always (center itself)
}

// ---------------- per-point feature GEMM: P = relu(bn(feat)) @ Wfeat^T ----------------
__global__ void __launch_bounds__(256) gemmP_kernel(const float* __restrict__ feat,
                                                    const float* __restrict__ bn_mean,
                                                    const float* __restrict__ bn_beta) {
    __shared__ float As[16][68];
    __shared__ float Bs[16][68];

    const int bm = blockIdx.x * 64;
    const int bn = blockIdx.y * 64;
    const int tid = threadIdx.x;

    const int row = tid >> 4;
    const int col = tid & 15;
    const int lm  = tid >> 2;
    const int lk4 = (tid & 3) * 4;
    const int kb  = tid >> 4;
    const int nb4 = (tid & 15) * 4;

    float acc[4][4];
#pragma unroll
    for (int i = 0; i < 4; i++)
#pragma unroll
        for (int j = 0; j < 4; j++) acc[i][j] = 0.f;

    for (int k0 = 0; k0 < CFEAT; k0 += 16) {
        float4 a4 = *(const float4*)(feat + (size_t)(bm + lm) * CFEAT + k0 + lk4);
        float av[4] = {a4.x, a4.y, a4.z, a4.w};
#pragma unroll
        for (int i = 0; i < 4; i++) {
            int c = k0 + lk4 + i + 3;
            float v = (av[i] - bn_mean[c]) * g_scale[c] + bn_beta[c];
            As[lk4 + i][lm] = fmaxf(v, 0.f);
        }
        float4 b4 = *(const float4*)(g_Wt + (size_t)(k0 + kb + 3) * COUT + bn + nb4);
        *(float4*)&Bs[kb][nb4] = b4;
        __syncthreads();

#pragma unroll
        for (int k = 0; k < 16; k++) {
            float4 a = *(float4*)&As[k][row * 4];
            float4 bq = *(float4*)&Bs[k][col * 4];
            float ar[4] = {a.x, a.y, a.z, a.w};
            float br[4] = {bq.x, bq.y, bq.z, bq.w};
#pragma unroll
            for (int i = 0; i < 4; i++)
#pragma unroll
                for (int j = 0; j < 4; j++) acc[i][j] += ar[i] * br[j];
        }
        __syncthreads();
    }

#pragma unroll
    for (int i = 0; i < 4; i++) {
        float4 o4 = make_float4(acc[i][0], acc[i][1], acc[i][2], acc[i][3]);
        *(float4*)(g_P + (size_t)(bm + row * 4 + i) * COUT + bn + col * 4) = o4;
    }
}

// ---------------- combine: gather P + xyz part, max over samples, bias, transpose ----------------
__global__ void __launch_bounds__(256) combine_kernel(const float* __restrict__ xyz,
                                                      const float* __restrict__ bias,
                                                      const float* __restrict__ bn_mean,
                                                      const float* __restrict__ bn_beta,
                                                      float* __restrict__ out_feat) {
    const int g = blockIdx.x;          // 0..8191
    const int b = g >> 10;
    const int s = g & 1023;
    const int o = threadIdx.x;         // 0..255

    __shared__ float t0[NSAMPLE], t1[NSAMPLE], t2[NSAMPLE];
    __shared__ int sidx[NSAMPLE];

    if (o < NSAMPLE) {
        int id = g_gidx[(size_t)g * NSAMPLE + o];
        sidx[o] = id;
        const float* Xp = xyz + ((size_t)b * NPTS + id) * 3;
        float cx = g_cent[(size_t)g * 3 + 0];
        float cy = g_cent[(size_t)g * 3 + 1];
        float cz = g_cent[(size_t)g * 3 + 2];
        float gx = __fsub_rn(Xp[0], cx);
        float gy = __fsub_rn(Xp[1], cy);
        float gz = __fsub_rn(Xp[2], cz);
        t0[o] = fmaxf((gx - bn_mean[0]) * g_scale[0] + bn_beta[0], 0.f);
        t1[o] = fmaxf((gy - bn_mean[1]) * g_scale[1] + bn_beta[1], 0.f);
        t2[o] = fmaxf((gz - bn_mean[2]) * g_scale[2] + bn_beta[2], 0.f);
    }
    __syncthreads();

    const float w0 = g_Wt[0 * COUT + o];
    const float w1 = g_Wt[1 * COUT + o];
    const float w2 = g_Wt[2 * COUT + o];
    const float* Pb = g_P + (size_t)b * NPTS * COUT;

    float acc = -3.402823466e+38f;
#pragma unroll 8
    for (int k = 0; k < NSAMPLE; k++) {
        float v = Pb[(size_t)sidx[k] * COUT + o];
        v = fmaf(w0, t0[k], v);
        v = fmaf(w1, t1[k], v);
        v = fmaf(w2, t2[k], v);
        acc = fmaxf(acc, v);
    }
    out_feat[((size_t)b * COUT + o) * NPOINT + s] = acc + bias[o];
}

// ---------------- launch: side stream runs prep+gemmP under FPS ----------------
extern "C" void kernel_launch(void* const* d_in, const int* in_sizes, int n_in,
                              void* d_out, int out_size) {
    const float* xyz   = (const float*)d_in[0];
    const float* feat  = (const float*)d_in[1];
    const float* W     = (const float*)d_in[2];
    const float* bias  = (const float*)d_in[3];
    const float* gamma = (const float*)d_in[4];
    const float* beta  = (const float*)d_in[5];
    const float* mean  = (const float*)d_in[6];
    const float* var   = (const float*)d_in[7];

    float* out = (float*)d_out;
    float* out_feat = out + ((size_t)out_size - (size_t)BATCH * COUT * NPOINT);

    cudaStream_t side;
    cudaEvent_t evFork, evPrep, evJoin;
    cudaStreamCreateWithFlags(&side, cudaStreamNonBlocking);
    cudaEventCreateWithFlags(&evFork, cudaEventDisableTiming);
    cudaEventCreateWithFlags(&evPrep, cudaEventDisableTiming);
    cudaEventCreateWithFlags(&evJoin, cudaEventDisableTiming);

    init_kernel<<<(CIN * COUT + 255) / 256, 256>>>(W, gamma, var);

    // fork: side branch = prep (xyz float4 pad) then gemmP; both independent of FPS
    cudaEventRecord(evFork, 0);
    cudaStreamWaitEvent(side, evFork, 0);
    prep_kernel<<<(BATCH * NPTS + 255) / 256, 256, 0, side>>>(xyz);
    cudaEventRecord(evPrep, side);
    gemmP_kernel<<<dim3((BATCH * NPTS) / 64, COUT / 64), 256, 0, side>>>(feat, mean, beta);
    cudaEventRecord(evJoin, side);

    // main branch: fps -> (wait prep) ballq
    fps_kernel<<<BATCH, 128>>>(xyz, out);
    cudaStreamWaitEvent(0, evPrep, 0);
    ballq_kernel<<<BATCH * 32, 1024>>>();

    // join: combine needs gemmP + ballq
    cudaStreamWaitEvent(0, evJoin, 0);
    combine_kernel<<<BATCH * NPOINT, 256>>>(xyz, bias, mean, beta, out_feat);
}

// round 8
// speedup vs baseline: 1.0091x; 1.0091x over previous
#include <cuda_runtime.h>
#include <cuda_bf16.h>
#include <cstdint>

#define BATCH 8
#define NPTS  4096
#define CFEAT 128
#define NPOINT 1024
#define NSAMPLE 32
#define COUT  256
#define CIN   131   // 3 + 128

typedef unsigned long long u64;

// ---------------- scratch (device globals; no allocation allowed) ----------------
__device__ float g_P[BATCH * NPTS * COUT];          // 33.5 MB  per-point feature GEMM result
__device__ int   g_gidx[BATCH * NPOINT * NSAMPLE];  // ball query indices
__device__ float g_cent[BATCH * NPOINT * 3];        // new_xyz copy for device use
__device__ float g_scale[CIN];                      // gamma / sqrt(var+eps)
__device__ float g_Wt[CIN * COUT];                  // W transposed

// ---------------- packed f32x2 helpers (bit-identical to scalar rn ops) ----------------
__device__ __forceinline__ u64 f2_add(u64 a, u64 b) {
    u64 r; asm("add.rn.f32x2 %0,%1,%2;" : "=l"(r) : "l"(a), "l"(b)); return r;
}
__device__ __forceinline__ u64 f2_mul(u64 a, u64 b) {
    u64 r; asm("mul.rn.f32x2 %0,%1,%2;" : "=l"(r) : "l"(a), "l"(b)); return r;
}
__device__ __forceinline__ u64 f2_pack(float lo, float hi) {
    u64 r; asm("mov.b64 %0,{%1,%2};" : "=l"(r) : "f"(lo), "f"(hi)); return r;
}
__device__ __forceinline__ void f2_unpack(u64 v, float& lo, float& hi) {
    asm("mov.b64 {%0,%1},%2;" : "=f"(lo), "=f"(hi) : "l"(v));
}

// ---------------- init: BN scale + W transpose ----------------
__global__ void init_kernel(const float* __restrict__ W,
                            const float* __restrict__ gamma,
                            const float* __restrict__ var) {
    int idx = blockIdx.x * blockDim.x + threadIdx.x;
    if (idx < CIN * COUT) {
        int o = idx & 255;
        int c = idx >> 8;
        g_Wt[c * COUT + o] = W[o * CIN + c];
    }
    if (idx < CIN) {
        g_scale[idx] = gamma[idx] / sqrtf(var[idx] + 1e-5f);
    }
}

// ---------------- furthest point sampling ----------------
// R2 structure (128 threads, 32 pts/thread, f32x2 exact arithmetic, single
// barrier) with the serial argmax chain split into 8 independent chains
// (4 links each) merged via packed u64 keys. Tie-break = lowest index at
// every level (within-chain: ascending indices + strict >; cross-chain and
// cross-warp: key = bits<<32 | ~idx, max-reduce).
__global__ void __launch_bounds__(128, 1) fps_kernel(const float* __restrict__ xyz,
                                                     float* __restrict__ out_xyz) {
    const int b = blockIdx.x;
    const float* X = xyz + (size_t)b * NPTS * 3;
    const int t    = threadIdx.x;
    const int lane = t & 31;
    const int wid  = t >> 5;
    const int base = t * 32;

    u64 PX[16], PY[16], PZ[16];
    float mind[32];
#pragma unroll
    for (int i = 0; i < 16; i++) {
        int p0 = base + 2 * i;
        float x0 = X[p0 * 3 + 0], y0 = X[p0 * 3 + 1], z0 = X[p0 * 3 + 2];
        float x1 = X[p0 * 3 + 3], y1 = X[p0 * 3 + 4], z1 = X[p0 * 3 + 5];
        PX[i] = f2_pack(x0, x1);
        PY[i] = f2_pack(y0, y1);
        PZ[i] = f2_pack(z0, z1);
        mind[2 * i] = 1e10f;
        mind[2 * i + 1] = 1e10f;
    }

    __shared__ u64 s_part[2][4];

    float qx = X[0], qy = X[1], qz = X[2];
    if (t == 0) {
        size_t r = (size_t)(b * NPOINT) * 3;
        g_cent[r + 0] = qx; g_cent[r + 1] = qy; g_cent[r + 2] = qz;
        out_xyz[r + 0] = qx; out_xyz[r + 1] = qy; out_xyz[r + 2] = qz;
    }

    for (int it = 1; it < NPOINT; ++it) {
        const u64 nqx = f2_pack(-qx, -qx);
        const u64 nqy = f2_pack(-qy, -qy);
        const u64 nqz = f2_pack(-qz, -qz);

        // 8 independent argmax chains (breaks the 32-link serial pred chain)
        unsigned cb0 = 0u, cb1 = 0u, cb2 = 0u, cb3 = 0u;
        unsigned cb4 = 0u, cb5 = 0u, cb6 = 0u, cb7 = 0u;
        int ci0 = 0, ci1 = 0, ci2 = 0, ci3 = 0;
        int ci4 = 0, ci5 = 0, ci6 = 0, ci7 = 0;

#pragma unroll
        for (int i = 0; i < 16; i++) {
            u64 dx = f2_add(PX[i], nqx);
            u64 dy = f2_add(PY[i], nqy);
            u64 dz = f2_add(PZ[i], nqz);
            u64 s  = f2_add(f2_add(f2_mul(dx, dx), f2_mul(dy, dy)), f2_mul(dz, dz));
            float s0, s1;
            f2_unpack(s, s0, s1);
            mind[2 * i]     = fminf(mind[2 * i], s0);
            mind[2 * i + 1] = fminf(mind[2 * i + 1], s1);
            unsigned m0 = __float_as_uint(mind[2 * i]);
            unsigned m1 = __float_as_uint(mind[2 * i + 1]);
            // chain selection is compile-time (unrolled, i constant)
            if ((i & 3) == 0) {
                if (m0 > cb0) { cb0 = m0; ci0 = base + 2 * i; }
                if (m1 > cb4) { cb4 = m1; ci4 = base + 2 * i + 1; }
            } else if ((i & 3) == 1) {
                if (m0 > cb1) { cb1 = m0; ci1 = base + 2 * i; }
                if (m1 > cb5) { cb5 = m1; ci5 = base + 2 * i + 1; }
            } else if ((i & 3) == 2) {
                if (m0 > cb2) { cb2 = m0; ci2 = base + 2 * i; }
                if (m1 > cb6) { cb6 = m1; ci6 = base + 2 * i + 1; }
            } else {
                if (m0 > cb3) { cb3 = m0; ci3 = base + 2 * i; }
                if (m1 > cb7) { cb7 = m1; ci7 = base + 2 * i + 1; }
            }
        }

        // merge 8 chains via packed keys (max bits, then lowest index)
        u64 k0 = ((u64)cb0 << 32) | (unsigned)(~ci0);
        u64 k1 = ((u64)cb1 << 32) | (unsigned)(~ci1);
        u64 k2 = ((u64)cb2 << 32) | (unsigned)(~ci2);
        u64 k3 = ((u64)cb3 << 32) | (unsigned)(~ci3);
        u64 k4 = ((u64)cb4 << 32) | (unsigned)(~ci4);
        u64 k5 = ((u64)cb5 << 32) | (unsigned)(~ci5);
        u64 k6 = ((u64)cb6 << 32) | (unsigned)(~ci6);
        u64 k7 = ((u64)cb7 << 32) | (unsigned)(~ci7);
        u64 ka = k0 > k1 ? k0 : k1;
        u64 kb2_ = k2 > k3 ? k2 : k3;
        u64 kc = k4 > k5 ? k4 : k5;
        u64 kd = k6 > k7 ? k6 : k7;
        u64 ke = ka > kb2_ ? ka : kb2_;
        u64 kf = kc > kd ? kc : kd;
        u64 kt = ke > kf ? ke : kf;
        unsigned bb = (unsigned)(kt >> 32);
        int bi = (int)(~(unsigned)kt);

        // warp argmax (ties -> lowest lane -> lowest index)
        unsigned wmax = __reduce_max_sync(0xffffffffu, bb);
        unsigned ball = __ballot_sync(0xffffffffu, bb == wmax);
        int src = __ffs(ball) - 1;
        int wbi = __shfl_sync(0xffffffffu, bi, src);
        if (lane == 0)
            s_part[it & 1][wid] = ((u64)wmax << 32) | (unsigned)(~wbi);
        __syncthreads();

        // every thread resolves the block winner itself (no 2nd barrier)
        u64 w0 = s_part[it & 1][0];
        u64 w1 = s_part[it & 1][1];
        u64 w2 = s_part[it & 1][2];
        u64 w3 = s_part[it & 1][3];
        u64 win = w0;
        if (w1 > win) win = w1;
        if (w2 > win) win = w2;
        if (w3 > win) win = w3;
        int li = (int)(~(unsigned)win);

        qx = X[li * 3 + 0]; qy = X[li * 3 + 1]; qz = X[li * 3 + 2];
        if (t == 0) {
            size_t r = (size_t)(b * NPOINT + it) * 3;
            g_cent[r + 0] = qx; g_cent[r + 1] = qy; g_cent[r + 2] = qz;
            out_xyz[r + 0] = qx; out_xyz[r + 1] = qy; out_xyz[r + 2] = qz;
        }
    }
}

// ---------------- ball query: warp per center (R6 proven version) ----------------
__global__ void __launch_bounds__(1024) ballq_kernel(const float* __restrict__ xyz) {
    const int b    = blockIdx.x >> 5;                       // 256 blocks: 32 per batch
    const int s    = ((blockIdx.x & 31) << 5) + (threadIdx.x >> 5);
    const int lane = threadIdx.x & 31;
    const float* X = xyz + (size_t)b * NPTS * 3;

    const size_t g = (size_t)b * NPOINT + s;
    const float cx = g_cent[g * 3 + 0];
    const float cy = g_cent[g * 3 + 1];
    const float cz = g_cent[g * 3 + 2];
    int* out = g_gidx + g * NSAMPLE;

    const float R2 = (float)(0.1 * 0.1);

    int cnt = 0;
    int first = -1;
    for (int basej = 0; basej < NPTS; basej += 32) {
        int j = basej + lane;
        float dx = __fsub_rn(cx, X[j * 3 + 0]);
        float dy = __fsub_rn(cy, X[j * 3 + 1]);
        float dz = __fsub_rn(cz, X[j * 3 + 2]);
        float d2 = __fadd_rn(__fadd_rn(__fmul_rn(dx, dx), __fmul_rn(dy, dy)),
                             __fmul_rn(dz, dz));
        bool valid = d2 < R2;
        unsigned mask = __ballot_sync(0xffffffffu, valid);
        if (first < 0 && mask) first = basej + __ffs(mask) - 1;
        if (valid) {
            int pos = cnt + __popc(mask & ((1u << lane) - 1u));
            if (pos < NSAMPLE) out[pos] = j;
        }
        cnt += __popc(mask);
        if (cnt >= NSAMPLE) break;
    }
    if (lane >= cnt && lane < NSAMPLE) out[lane] = first;   // cnt>=1 always (center itself)
}

// ---------------- per-point feature GEMM: P = relu(bn(feat)) @ Wfeat^T ----------------
__global__ void __launch_bounds__(256) gemmP_kernel(const float* __restrict__ feat,
                                                    const float* __restrict__ bn_mean,
                                                    const float* __restrict__ bn_beta) {
    __shared__ float As[16][68];
    __shared__ float Bs[16][68];

    const int bm = blockIdx.x * 64;
    const int bn = blockIdx.y * 64;
    const int tid = threadIdx.x;

    const int row = tid >> 4;
    const int col = tid & 15;
    const int lm  = tid >> 2;
    const int lk4 = (tid & 3) * 4;
    const int kb  = tid >> 4;
    const int nb4 = (tid & 15) * 4;

    float acc[4][4];
#pragma unroll
    for (int i = 0; i < 4; i++)
#pragma unroll
        for (int j = 0; j < 4; j++) acc[i][j] = 0.f;

    for (int k0 = 0; k0 < CFEAT; k0 += 16) {
        float4 a4 = *(const float4*)(feat + (size_t)(bm + lm) * CFEAT + k0 + lk4);
        float av[4] = {a4.x, a4.y, a4.z, a4.w};
#pragma unroll
        for (int i = 0; i < 4; i++) {
            int c = k0 + lk4 + i + 3;
            float v = (av[i] - bn_mean[c]) * g_scale[c] + bn_beta[c];
            As[lk4 + i][lm] = fmaxf(v, 0.f);
        }
        float4 b4 = *(const float4*)(g_Wt + (size_t)(k0 + kb + 3) * COUT + bn + nb4);
        *(float4*)&Bs[kb][nb4] = b4;
        __syncthreads();

#pragma unroll
        for (int k = 0; k < 16; k++) {
            float4 a = *(float4*)&As[k][row * 4];
            float4 bq = *(float4*)&Bs[k][col * 4];
            float ar[4] = {a.x, a.y, a.z, a.w};
            float br[4] = {bq.x, bq.y, bq.z, bq.w};
#pragma unroll
            for (int i = 0; i < 4; i++)
#pragma unroll
                for (int j = 0; j < 4; j++) acc[i][j] += ar[i] * br[j];
        }
        __syncthreads();
    }

#pragma unroll
    for (int i = 0; i < 4; i++) {
        float4 o4 = make_float4(acc[i][0], acc[i][1], acc[i][2], acc[i][3]);
        *(float4*)(g_P + (size_t)(bm + row * 4 + i) * COUT + bn + col * 4) = o4;
    }
}

// ---------------- combine: gather P + xyz part, max over samples, bias, transpose ----------------
__global__ void __launch_bounds__(256) combine_kernel(const float* __restrict__ xyz,
                                                      const float* __restrict__ bias,
                                                      const float* __restrict__ bn_mean,
                                                      const float* __restrict__ bn_beta,
                                                      float* __restrict__ out_feat) {
    const int g = blockIdx.x;          // 0..8191
    const int b = g >> 10;
    const int s = g & 1023;
    const int o = threadIdx.x;         // 0..255

    __shared__ float t0[NSAMPLE], t1[NSAMPLE], t2[NSAMPLE];
    __shared__ int sidx[NSAMPLE];

    if (o < NSAMPLE) {
        int id = g_gidx[(size_t)g * NSAMPLE + o];
        sidx[o] = id;
        const float* Xp = xyz + ((size_t)b * NPTS + id) * 3;
        float cx = g_cent[(size_t)g * 3 + 0];
        float cy = g_cent[(size_t)g * 3 + 1];
        float cz = g_cent[(size_t)g * 3 + 2];
        float gx = __fsub_rn(Xp[0], cx);
        float gy = __fsub_rn(Xp[1], cy);
        float gz = __fsub_rn(Xp[2], cz);
        t0[o] = fmaxf((gx - bn_mean[0]) * g_scale[0] + bn_beta[0], 0.f);
        t1[o] = fmaxf((gy - bn_mean[1]) * g_scale[1] + bn_beta[1], 0.f);
        t2[o] = fmaxf((gz - bn_mean[2]) * g_scale[2] + bn_beta[2], 0.f);
    }
    __syncthreads();

    const float w0 = g_Wt[0 * COUT + o];
    const float w1 = g_Wt[1 * COUT + o];
    const float w2 = g_Wt[2 * COUT + o];
    const float* Pb = g_P + (size_t)b * NPTS * COUT;

    float acc = -3.402823466e+38f;
#pragma unroll 8
    for (int k = 0; k < NSAMPLE; k++) {
        float v = Pb[(size_t)sidx[k] * COUT + o];
        v = fmaf(w0, t0[k], v);
        v = fmaf(w1, t1[k], v);
        v = fmaf(w2, t2[k], v);
        acc = fmaxf(acc, v);
    }
    out_feat[((size_t)b * COUT + o) * NPOINT + s] = acc + bias[o];
}

// ---------------- launch: fork gemmP onto a side stream so it overlaps FPS ----------------
extern "C" void kernel_launch(void* const* d_in, const int* in_sizes, int n_in,
                              void* d_out, int out_size) {
    const float* xyz   = (const float*)d_in[0];
    const float* feat  = (const float*)d_in[1];
    const float* W     = (const float*)d_in[2];
    const float* bias  = (const float*)d_in[3];
    const float* gamma = (const float*)d_in[4];
    const float* beta  = (const float*)d_in[5];
    const float* mean  = (const float*)d_in[6];
    const float* var   = (const float*)d_in[7];

    float* out = (float*)d_out;
    float* out_feat = out + ((size_t)out_size - (size_t)BATCH * COUT * NPOINT);

    cudaStream_t side;
    cudaEvent_t evFork, evJoin;
    cudaStreamCreateWithFlags(&side, cudaStreamNonBlocking);
    cudaEventCreateWithFlags(&evFork, cudaEventDisableTiming);
    cudaEventCreateWithFlags(&evJoin, cudaEventDisableTiming);

    init_kernel<<<(CIN * COUT + 255) / 256, 256>>>(W, gamma, var);

    // fork: gemmP depends only on init
    cudaEventRecord(evFork, 0);
    cudaStreamWaitEvent(side, evFork, 0);
    gemmP_kernel<<<dim3((BATCH * NPTS) / 64, COUT / 64), 256, 0, side>>>(feat, mean, beta);
    cudaEventRecord(evJoin, side);

    // main branch: fps -> ballq
    fps_kernel<<<BATCH, 128>>>(xyz, out);
    ballq_kernel<<<BATCH * 32, 1024>>>(xyz);

    // join: combine needs gemmP + ballq
    cudaStreamWaitEvent(0, evJoin, 0);
    combine_kernel<<<BATCH * NPOINT, 256>>>(xyz, bias, mean, beta, out_feat);
}

// round 9
// speedup vs baseline: 1.1336x; 1.1234x over previous
#include <cuda_runtime.h>
#include <cuda_bf16.h>
#include <cstdint>

#define BATCH 8
#define NPTS  4096
#define CFEAT 128
#define NPOINT 1024
#define NSAMPLE 32
#define COUT  256
#define CIN   131   // 3 + 128
#define NCELL 1000  // 10x10x10
#define SENT  0x7FFFFFFF

typedef unsigned long long u64;

// ---------------- scratch (device globals; no allocation allowed) ----------------
__device__ float g_P[BATCH * NPTS * COUT];          // per-point feature GEMM result
__device__ int   g_gidx[BATCH * NPOINT * NSAMPLE];  // ball query indices
__device__ float g_cent[BATCH * NPOINT * 3];        // new_xyz copy for device use
__device__ float g_scale[CIN];                      // gamma / sqrt(var+eps)
__device__ float g_Wt[CIN * COUT];                  // W transposed
__device__ int   g_cellStart[BATCH * (NCELL + 1)];  // bin CSR offsets
__device__ int   g_pointIdx[BATCH * NPTS];          // point ids grouped by cell

// ---------------- packed f32x2 helpers (bit-identical to scalar rn ops) ----------------
__device__ __forceinline__ u64 f2_add(u64 a, u64 b) {
    u64 r; asm("add.rn.f32x2 %0,%1,%2;" : "=l"(r) : "l"(a), "l"(b)); return r;
}
__device__ __forceinline__ u64 f2_mul(u64 a, u64 b) {
    u64 r; asm("mul.rn.f32x2 %0,%1,%2;" : "=l"(r) : "l"(a), "l"(b)); return r;
}
__device__ __forceinline__ u64 f2_pack(float lo, float hi) {
    u64 r; asm("mov.b64 %0,{%1,%2};" : "=l"(r) : "f"(lo), "f"(hi)); return r;
}
__device__ __forceinline__ void f2_unpack(u64 v, float& lo, float& hi) {
    asm("mov.b64 {%0,%1},%2;" : "=f"(lo), "=f"(hi) : "l"(v));
}

// ---------------- init: BN scale + W transpose ----------------
__global__ void init_kernel(const float* __restrict__ W,
                            const float* __restrict__ gamma,
                            const float* __restrict__ var) {
    int idx = blockIdx.x * blockDim.x + threadIdx.x;
    if (idx < CIN * COUT) {
        int o = idx & 255;
        int c = idx >> 8;
        g_Wt[c * COUT + o] = W[o * CIN + c];
    }
    if (idx < CIN) {
        g_scale[idx] = gamma[idx] / sqrtf(var[idx] + 1e-5f);
    }
}

// ---------------- bin points into 10x10x10 grid (one block per batch) ----------------
__global__ void __launch_bounds__(1024) bin_kernel(const float* __restrict__ xyz) {
    __shared__ int hist[NCELL];
    __shared__ int off[NCELL];
    __shared__ int tmp[1024];

    const int b = blockIdx.x;
    const int t = threadIdx.x;
    const float* X = xyz + (size_t)b * NPTS * 3;

    if (t < NCELL) hist[t] = 0;
    __syncthreads();

    int cell[NPTS / 1024];
#pragma unroll
    for (int r = 0; r < NPTS / 1024; r++) {
        int i = t + r * 1024;
        float x = X[i * 3 + 0], y = X[i * 3 + 1], z = X[i * 3 + 2];
        int cx = (int)(x * 9.99f);
        int cy = (int)(y * 9.99f);
        int cz = (int)(z * 9.99f);
        cell[r] = (cx * 10 + cy) * 10 + cz;
        atomicAdd(&hist[cell[r]], 1);
    }
    __syncthreads();

    // block-wide inclusive scan (Hillis-Steele) over 1024 slots (bins 0..999)
    int v = (t < NCELL) ? hist[t] : 0;
    tmp[t] = v;
    __syncthreads();
    for (int d = 1; d < 1024; d <<= 1) {
        int add = (t >= d) ? tmp[t - d] : 0;
        __syncthreads();
        tmp[t] += add;
        __syncthreads();
    }
    if (t < NCELL) {
        int ex = tmp[t] - v;                 // exclusive
        off[t] = ex;
        g_cellStart[b * (NCELL + 1) + t] = ex;
    }
    if (t == 0) g_cellStart[b * (NCELL + 1) + NCELL] = NPTS;
    __syncthreads();

#pragma unroll
    for (int r = 0; r < NPTS / 1024; r++) {
        int i = t + r * 1024;
        int pos = atomicAdd(&off[cell[r]], 1);
        g_pointIdx[b * NPTS + pos] = i;      // unordered within cell; sorted later
    }
}

// ---------------- furthest point sampling (R2 exact — frozen) ----------------
__global__ void __launch_bounds__(128, 1) fps_kernel(const float* __restrict__ xyz,
                                                     float* __restrict__ out_xyz) {
    const int b = blockIdx.x;
    const float* X = xyz + (size_t)b * NPTS * 3;
    const int t    = threadIdx.x;
    const int lane = t & 31;
    const int wid  = t >> 5;
    const int base = t * 32;

    u64 PX[16], PY[16], PZ[16];
    float mind[32];
#pragma unroll
    for (int i = 0; i < 16; i++) {
        int p0 = base + 2 * i;
        float x0 = X[p0 * 3 + 0], y0 = X[p0 * 3 + 1], z0 = X[p0 * 3 + 2];
        float x1 = X[p0 * 3 + 3], y1 = X[p0 * 3 + 4], z1 = X[p0 * 3 + 5];
        PX[i] = f2_pack(x0, x1);
        PY[i] = f2_pack(y0, y1);
        PZ[i] = f2_pack(z0, z1);
        mind[2 * i] = 1e10f;
        mind[2 * i + 1] = 1e10f;
    }

    __shared__ u64 s_part[2][4];

    float qx = X[0], qy = X[1], qz = X[2];
    if (t == 0) {
        size_t r = (size_t)(b * NPOINT) * 3;
        g_cent[r + 0] = qx; g_cent[r + 1] = qy; g_cent[r + 2] = qz;
        out_xyz[r + 0] = qx; out_xyz[r + 1] = qy; out_xyz[r + 2] = qz;
    }

    for (int it = 1; it < NPOINT; ++it) {
        const u64 nqx = f2_pack(-qx, -qx);
        const u64 nqy = f2_pack(-qy, -qy);
        const u64 nqz = f2_pack(-qz, -qz);

        unsigned bb = 0u;   // best mind bits (nonneg float -> bits monotonic)
        int bi = 0;
#pragma unroll
        for (int i = 0; i < 16; i++) {
            u64 dx = f2_add(PX[i], nqx);
            u64 dy = f2_add(PY[i], nqy);
            u64 dz = f2_add(PZ[i], nqz);
            u64 s  = f2_add(f2_add(f2_mul(dx, dx), f2_mul(dy, dy)), f2_mul(dz, dz));
            float s0, s1;
            f2_unpack(s, s0, s1);
            mind[2 * i]     = fminf(mind[2 * i], s0);
            mind[2 * i + 1] = fminf(mind[2 * i + 1], s1);
            unsigned m0 = __float_as_uint(mind[2 * i]);
            if (m0 > bb) { bb = m0; bi = base + 2 * i; }       // strict > keeps earliest index
            unsigned m1 = __float_as_uint(mind[2 * i + 1]);
            if (m1 > bb) { bb = m1; bi = base + 2 * i + 1; }
        }

        unsigned wmax = __reduce_max_sync(0xffffffffu, bb);
        unsigned ball = __ballot_sync(0xffffffffu, bb == wmax);
        int src = __ffs(ball) - 1;
        int wbi = __shfl_sync(0xffffffffu, bi, src);
        if (lane == 0)
            s_part[it & 1][wid] = ((u64)wmax << 32) | (unsigned)(~wbi);
        __syncthreads();

        u64 w0 = s_part[it & 1][0];
        u64 w1 = s_part[it & 1][1];
        u64 w2 = s_part[it & 1][2];
        u64 w3 = s_part[it & 1][3];
        u64 win = w0;
        if (w1 > win) win = w1;
        if (w2 > win) win = w2;
        if (w3 > win) win = w3;
        int li = (int)(~(unsigned)win);

        qx = X[li * 3 + 0]; qy = X[li * 3 + 1]; qz = X[li * 3 + 2];
        if (t == 0) {
            size_t r = (size_t)(b * NPOINT + it) * 3;
            g_cent[r + 0] = qx; g_cent[r + 1] = qy; g_cent[r + 2] = qz;
            out_xyz[r + 0] = qx; out_xyz[r + 1] = qy; out_xyz[r + 2] = qz;
        }
    }
}

// ---------------- ball query via grid bins: warp per center ----------------
// Collect all valid candidates from the 27 neighbor cells (predicate bit-identical
// to reference), then bitonic-sort indices ascending and take the first 32.
// Matches reference exactly: 32 smallest valid indices, padded with the smallest.
__global__ void __launch_bounds__(256) ballq_kernel(const float* __restrict__ xyz) {
    __shared__ int cand[8][64];

    const int w    = threadIdx.x >> 5;
    const int lane = threadIdx.x & 31;
    const int g    = blockIdx.x * 8 + w;       // 0..8191
    const int b    = g >> 10;
    const float* X = xyz + (size_t)b * NPTS * 3;
    const int* CS  = g_cellStart + b * (NCELL + 1);
    const int* PI  = g_pointIdx + b * NPTS;

    const float cx = g_cent[(size_t)g * 3 + 0];
    const float cy = g_cent[(size_t)g * 3 + 1];
    const float cz = g_cent[(size_t)g * 3 + 2];
    int* out = g_gidx + (size_t)g * NSAMPLE;

    const float R2 = (float)(0.1 * 0.1);

    int icx = (int)(cx * 9.99f);
    int icy = (int)(cy * 9.99f);
    int icz = (int)(cz * 9.99f);
    int x0 = max(icx - 1, 0), x1 = min(icx + 1, 9);
    int y0 = max(icy - 1, 0), y1 = min(icy + 1, 9);
    int z0 = max(icz - 1, 0), z1 = min(icz + 1, 9);

    int cnt = 0;
    for (int sx = x0; sx <= x1; sx++) {
        for (int sy = y0; sy <= y1; sy++) {
            int cb = (sx * 10 + sy) * 10;
            int j0 = CS[cb + z0];
            int j1 = CS[cb + z1 + 1];               // z-range is contiguous
            for (int jj = j0; jj < j1; jj += 32) {
                int j = jj + lane;
                bool valid = false;
                int idx = 0;
                if (j < j1) {
                    idx = PI[j];
                    float dx = __fsub_rn(cx, X[idx * 3 + 0]);
                    float dy = __fsub_rn(cy, X[idx * 3 + 1]);
                    float dz = __fsub_rn(cz, X[idx * 3 + 2]);
                    float d2 = __fadd_rn(__fadd_rn(__fmul_rn(dx, dx), __fmul_rn(dy, dy)),
                                         __fmul_rn(dz, dz));
                    valid = d2 < R2;
                }
                unsigned m = __ballot_sync(0xffffffffu, valid);
                if (valid) {
                    int pos = cnt + __popc(m & ((1u << lane) - 1u));
                    if (pos < 64) cand[w][pos] = idx;
                }
                cnt += __popc(m);
            }
        }
    }
    __syncwarp();

    int mcnt = cnt < 64 ? cnt : 64;
    int ca = (2 * lane     < mcnt) ? cand[w][2 * lane]     : SENT;
    int cb = (2 * lane + 1 < mcnt) ? cand[w][2 * lane + 1] : SENT;

    // bitonic sort of 64 ints, 2 per lane (element e = 2*lane + r), ascending
#pragma unroll
    for (int k = 2; k <= 64; k <<= 1) {
#pragma unroll
        for (int j = k >> 1; j >= 2; j >>= 1) {
            int jl = j >> 1;
            int pa = __shfl_xor_sync(0xffffffffu, ca, jl);
            int pb = __shfl_xor_sync(0xffffffffu, cb, jl);
            bool up = (((2 * lane) & k) == 0);
            bool lower = ((lane & jl) == 0);
            bool kmin = (up == lower);
            ca = kmin ? min(ca, pa) : max(ca, pa);
            cb = kmin ? min(cb, pb) : max(cb, pb);
        }
        {   // j == 1: intra-lane pair
            bool up = (((2 * lane) & k) == 0);
            int lo = min(ca, cb), hi = max(ca, cb);
            ca = up ? lo : hi;
            cb = up ? hi : lo;
        }
    }

    int first = __shfl_sync(0xffffffffu, ca, 0);   // smallest valid index (cnt>=1 always)
    if (lane < 16) {
        int v0 = (ca == SENT) ? first : ca;
        int v1 = (cb == SENT) ? first : cb;
        out[2 * lane + 0] = v0;
        out[2 * lane + 1] = v1;
    }
}

// ---------------- per-point feature GEMM: P = relu(bn(feat)) @ Wfeat^T ----------------
__global__ void __launch_bounds__(256) gemmP_kernel(const float* __restrict__ feat,
                                                    const float* __restrict__ bn_mean,
                                                    const float* __restrict__ bn_beta) {
    __shared__ float As[16][68];
    __shared__ float Bs[16][68];

    const int bm = blockIdx.x * 64;
    const int bn = blockIdx.y * 64;
    const int tid = threadIdx.x;

    const int row = tid >> 4;
    const int col = tid & 15;
    const int lm  = tid >> 2;
    const int lk4 = (tid & 3) * 4;
    const int kb  = tid >> 4;
    const int nb4 = (tid & 15) * 4;

    float acc[4][4];
#pragma unroll
    for (int i = 0; i < 4; i++)
#pragma unroll
        for (int j = 0; j < 4; j++) acc[i][j] = 0.f;

    for (int k0 = 0; k0 < CFEAT; k0 += 16) {
        float4 a4 = *(const float4*)(feat + (size_t)(bm + lm) * CFEAT + k0 + lk4);
        float av[4] = {a4.x, a4.y, a4.z, a4.w};
#pragma unroll
        for (int i = 0; i < 4; i++) {
            int c = k0 + lk4 + i + 3;
            float v = (av[i] - bn_mean[c]) * g_scale[c] + bn_beta[c];
            As[lk4 + i][lm] = fmaxf(v, 0.f);
        }
        float4 b4 = *(const float4*)(g_Wt + (size_t)(k0 + kb + 3) * COUT + bn + nb4);
        *(float4*)&Bs[kb][nb4] = b4;
        __syncthreads();

#pragma unroll
        for (int k = 0; k < 16; k++) {
            float4 a = *(float4*)&As[k][row * 4];
            float4 bq = *(float4*)&Bs[k][col * 4];
            float ar[4] = {a.x, a.y, a.z, a.w};
            float br[4] = {bq.x, bq.y, bq.z, bq.w};
#pragma unroll
            for (int i = 0; i < 4; i++)
#pragma unroll
                for (int j = 0; j < 4; j++) acc[i][j] += ar[i] * br[j];
        }
        __syncthreads();
    }

#pragma unroll
    for (int i = 0; i < 4; i++) {
        float4 o4 = make_float4(acc[i][0], acc[i][1], acc[i][2], acc[i][3]);
        *(float4*)(g_P + (size_t)(bm + row * 4 + i) * COUT + bn + col * 4) = o4;
    }
}

// ---------------- combine: gather P + xyz part, max over samples, bias, transpose ----------------
__global__ void __launch_bounds__(256) combine_kernel(const float* __restrict__ xyz,
                                                      const float* __restrict__ bias,
                                                      const float* __restrict__ bn_mean,
                                                      const float* __restrict__ bn_beta,
                                                      float* __restrict__ out_feat) {
    const int g = blockIdx.x;          // 0..8191
    const int b = g >> 10;
    const int s = g & 1023;
    const int o = threadIdx.x;         // 0..255

    __shared__ float t0[NSAMPLE], t1[NSAMPLE], t2[NSAMPLE];
    __shared__ int sidx[NSAMPLE];

    if (o < NSAMPLE) {
        int id = g_gidx[(size_t)g * NSAMPLE + o];
        sidx[o] = id;
        const float* Xp = xyz + ((size_t)b * NPTS + id) * 3;
        float cx = g_cent[(size_t)g * 3 + 0];
        float cy = g_cent[(size_t)g * 3 + 1];
        float cz = g_cent[(size_t)g * 3 + 2];
        float gx = __fsub_rn(Xp[0], cx);
        float gy = __fsub_rn(Xp[1], cy);
        float gz = __fsub_rn(Xp[2], cz);
        t0[o] = fmaxf((gx - bn_mean[0]) * g_scale[0] + bn_beta[0], 0.f);
        t1[o] = fmaxf((gy - bn_mean[1]) * g_scale[1] + bn_beta[1], 0.f);
        t2[o] = fmaxf((gz - bn_mean[2]) * g_scale[2] + bn_beta[2], 0.f);
    }
    __syncthreads();

    const float w0 = g_Wt[0 * COUT + o];
    const float w1 = g_Wt[1 * COUT + o];
    const float w2 = g_Wt[2 * COUT + o];
    const float* Pb = g_P + (size_t)b * NPTS * COUT;

    float acc = -3.402823466e+38f;
#pragma unroll 8
    for (int k = 0; k < NSAMPLE; k++) {
        float v = Pb[(size_t)sidx[k] * COUT + o];
        v = fmaf(w0, t0[k], v);
        v = fmaf(w1, t1[k], v);
        v = fmaf(w2, t2[k], v);
        acc = fmaxf(acc, v);
    }
    out_feat[((size_t)b * COUT + o) * NPOINT + s] = acc + bias[o];
}

// ---------------- launch: side stream runs bin + gemmP under FPS ----------------
extern "C" void kernel_launch(void* const* d_in, const int* in_sizes, int n_in,
                              void* d_out, int out_size) {
    const float* xyz   = (const float*)d_in[0];
    const float* feat  = (const float*)d_in[1];
    const float* W     = (const float*)d_in[2];
    const float* bias  = (const float*)d_in[3];
    const float* gamma = (const float*)d_in[4];
    const float* beta  = (const float*)d_in[5];
    const float* mean  = (const float*)d_in[6];
    const float* var   = (const float*)d_in[7];

    float* out = (float*)d_out;
    float* out_feat = out + ((size_t)out_size - (size_t)BATCH * COUT * NPOINT);

    cudaStream_t side;
    cudaEvent_t evFork, evBin, evJoin;
    cudaStreamCreateWithFlags(&side, cudaStreamNonBlocking);
    cudaEventCreateWithFlags(&evFork, cudaEventDisableTiming);
    cudaEventCreateWithFlags(&evBin, cudaEventDisableTiming);
    cudaEventCreateWithFlags(&evJoin, cudaEventDisableTiming);

    init_kernel<<<(CIN * COUT + 255) / 256, 256>>>(W, gamma, var);

    // fork: side branch = binning then gemmP (both independent of FPS, hidden under it)
    cudaEventRecord(evFork, 0);
    cudaStreamWaitEvent(side, evFork, 0);
    bin_kernel<<<BATCH, 1024, 0, side>>>(xyz);
    cudaEventRecord(evBin, side);
    gemmP_kernel<<<dim3((BATCH * NPTS) / 64, COUT / 64), 256, 0, side>>>(feat, mean, beta);
    cudaEventRecord(evJoin, side);

    // main branch: fps -> (wait bins) ballq
    fps_kernel<<<BATCH, 128>>>(xyz, out);
    cudaStreamWaitEvent(0, evBin, 0);
    ballq_kernel<<<BATCH * NPOINT / 8, 256>>>(xyz);

    // join: combine needs gemmP + ballq
    cudaStreamWaitEvent(0, evJoin, 0);
    combine_kernel<<<BATCH * NPOINT, 256>>>(xyz, bias, mean, beta, out_feat);
}

// round 10
// speedup vs baseline: 1.1339x; 1.0003x over previous
#include <cuda_runtime.h>
#include <cuda_bf16.h>
#include <cstdint>

#define BATCH 8
#define NPTS  4096
#define CFEAT 128
#define NPOINT 1024
#define NSAMPLE 32
#define COUT  256
#define CIN   131   // 3 + 128
#define NCELL 1000  // 10x10x10
#define SENT  0x7FFFFFFF

typedef unsigned long long u64;

// ---------------- scratch (device globals; no allocation allowed) ----------------
__device__ float  g_P[BATCH * NPTS * COUT];          // per-point feature GEMM result
__device__ int    g_gidx[BATCH * NPOINT * NSAMPLE];  // ball query indices
__device__ float  g_cent[BATCH * NPOINT * 3];        // new_xyz copy for device use
__device__ float  g_scale[CIN];                      // gamma / sqrt(var+eps)
__device__ float  g_Wt[CIN * COUT];                  // W transposed
__device__ int    g_cellStart[BATCH * (NCELL + 1)];  // bin CSR offsets
__device__ float4 g_xyzBin[BATCH * NPTS];            // (x,y,z,orig_idx) in binned order

// ---------------- packed f32x2 helpers (bit-identical to scalar rn ops) ----------------
__device__ __forceinline__ u64 f2_add(u64 a, u64 b) {
    u64 r; asm("add.rn.f32x2 %0,%1,%2;" : "=l"(r) : "l"(a), "l"(b)); return r;
}
__device__ __forceinline__ u64 f2_mul(u64 a, u64 b) {
    u64 r; asm("mul.rn.f32x2 %0,%1,%2;" : "=l"(r) : "l"(a), "l"(b)); return r;
}
__device__ __forceinline__ u64 f2_pack(float lo, float hi) {
    u64 r; asm("mov.b64 %0,{%1,%2};" : "=l"(r) : "f"(lo), "f"(hi)); return r;
}
__device__ __forceinline__ void f2_unpack(u64 v, float& lo, float& hi) {
    asm("mov.b64 {%0,%1},%2;" : "=f"(lo), "=f"(hi) : "l"(v));
}

// ---------------- init: BN scale + W transpose ----------------
__global__ void init_kernel(const float* __restrict__ W,
                            const float* __restrict__ gamma,
                            const float* __restrict__ var) {
    int idx = blockIdx.x * blockDim.x + threadIdx.x;
    if (idx < CIN * COUT) {
        int o = idx & 255;
        int c = idx >> 8;
        g_Wt[c * COUT + o] = W[o * CIN + c];
    }
    if (idx < CIN) {
        g_scale[idx] = gamma[idx] / sqrtf(var[idx] + 1e-5f);
    }
}

// ---------------- bin points into 10x10x10 grid (one block per batch) ----------------
// Also scatters coords (+ original index in .w) into binned order so ballq
// streams candidates with coalesced LDG.128s.
__global__ void __launch_bounds__(1024) bin_kernel(const float* __restrict__ xyz) {
    __shared__ int hist[NCELL];
    __shared__ int off[NCELL];
    __shared__ int tmp[1024];

    const int b = blockIdx.x;
    const int t = threadIdx.x;
    const float* X = xyz + (size_t)b * NPTS * 3;

    if (t < NCELL) hist[t] = 0;
    __syncthreads();

    int   cell[NPTS / 1024];
    float px[NPTS / 1024], py[NPTS / 1024], pz[NPTS / 1024];
#pragma unroll
    for (int r = 0; r < NPTS / 1024; r++) {
        int i = t + r * 1024;
        px[r] = X[i * 3 + 0];
        py[r] = X[i * 3 + 1];
        pz[r] = X[i * 3 + 2];
        int cx = (int)(px[r] * 9.99f);
        int cy = (int)(py[r] * 9.99f);
        int cz = (int)(pz[r] * 9.99f);
        cell[r] = (cx * 10 + cy) * 10 + cz;
        atomicAdd(&hist[cell[r]], 1);
    }
    __syncthreads();

    // block-wide inclusive scan (Hillis-Steele) over 1024 slots (bins 0..999)
    int v = (t < NCELL) ? hist[t] : 0;
    tmp[t] = v;
    __syncthreads();
    for (int d = 1; d < 1024; d <<= 1) {
        int add = (t >= d) ? tmp[t - d] : 0;
        __syncthreads();
        tmp[t] += add;
        __syncthreads();
    }
    if (t < NCELL) {
        int ex = tmp[t] - v;                 // exclusive
        off[t] = ex;
        g_cellStart[b * (NCELL + 1) + t] = ex;
    }
    if (t == 0) g_cellStart[b * (NCELL + 1) + NCELL] = NPTS;
    __syncthreads();

#pragma unroll
    for (int r = 0; r < NPTS / 1024; r++) {
        int i = t + r * 1024;
        int pos = atomicAdd(&off[cell[r]], 1);
        g_xyzBin[b * NPTS + pos] = make_float4(px[r], py[r], pz[r], __int_as_float(i));
    }
}

// ---------------- furthest point sampling (R2 exact — frozen) ----------------
__global__ void __launch_bounds__(128, 1) fps_kernel(const float* __restrict__ xyz,
                                                     float* __restrict__ out_xyz) {
    const int b = blockIdx.x;
    const float* X = xyz + (size_t)b * NPTS * 3;
    const int t    = threadIdx.x;
    const int lane = t & 31;
    const int wid  = t >> 5;
    const int base = t * 32;

    u64 PX[16], PY[16], PZ[16];
    float mind[32];
#pragma unroll
    for (int i = 0; i < 16; i++) {
        int p0 = base + 2 * i;
        float x0 = X[p0 * 3 + 0], y0 = X[p0 * 3 + 1], z0 = X[p0 * 3 + 2];
        float x1 = X[p0 * 3 + 3], y1 = X[p0 * 3 + 4], z1 = X[p0 * 3 + 5];
        PX[i] = f2_pack(x0, x1);
        PY[i] = f2_pack(y0, y1);
        PZ[i] = f2_pack(z0, z1);
        mind[2 * i] = 1e10f;
        mind[2 * i + 1] = 1e10f;
    }

    __shared__ u64 s_part[2][4];

    float qx = X[0], qy = X[1], qz = X[2];
    if (t == 0) {
        size_t r = (size_t)(b * NPOINT) * 3;
        g_cent[r + 0] = qx; g_cent[r + 1] = qy; g_cent[r + 2] = qz;
        out_xyz[r + 0] = qx; out_xyz[r + 1] = qy; out_xyz[r + 2] = qz;
    }

    for (int it = 1; it < NPOINT; ++it) {
        const u64 nqx = f2_pack(-qx, -qx);
        const u64 nqy = f2_pack(-qy, -qy);
        const u64 nqz = f2_pack(-qz, -qz);

        unsigned bb = 0u;   // best mind bits (nonneg float -> bits monotonic)
        int bi = 0;
#pragma unroll
        for (int i = 0; i < 16; i++) {
            u64 dx = f2_add(PX[i], nqx);
            u64 dy = f2_add(PY[i], nqy);
            u64 dz = f2_add(PZ[i], nqz);
            u64 s  = f2_add(f2_add(f2_mul(dx, dx), f2_mul(dy, dy)), f2_mul(dz, dz));
            float s0, s1;
            f2_unpack(s, s0, s1);
            mind[2 * i]     = fminf(mind[2 * i], s0);
            mind[2 * i + 1] = fminf(mind[2 * i + 1], s1);
            unsigned m0 = __float_as_uint(mind[2 * i]);
            if (m0 > bb) { bb = m0; bi = base + 2 * i; }       // strict > keeps earliest index
            unsigned m1 = __float_as_uint(mind[2 * i + 1]);
            if (m1 > bb) { bb = m1; bi = base + 2 * i + 1; }
        }

        unsigned wmax = __reduce_max_sync(0xffffffffu, bb);
        unsigned ball = __ballot_sync(0xffffffffu, bb == wmax);
        int src = __ffs(ball) - 1;
        int wbi = __shfl_sync(0xffffffffu, bi, src);
        if (lane == 0)
            s_part[it & 1][wid] = ((u64)wmax << 32) | (unsigned)(~wbi);
        __syncthreads();

        u64 w0 = s_part[it & 1][0];
        u64 w1 = s_part[it & 1][1];
        u64 w2 = s_part[it & 1][2];
        u64 w3 = s_part[it & 1][3];
        u64 win = w0;
        if (w1 > win) win = w1;
        if (w2 > win) win = w2;
        if (w3 > win) win = w3;
        int li = (int)(~(unsigned)win);

        qx = X[li * 3 + 0]; qy = X[li * 3 + 1]; qz = X[li * 3 + 2];
        if (t == 0) {
            size_t r = (size_t)(b * NPOINT + it) * 3;
            g_cent[r + 0] = qx; g_cent[r + 1] = qy; g_cent[r + 2] = qz;
            out_xyz[r + 0] = qx; out_xyz[r + 1] = qy; out_xyz[r + 2] = qz;
        }
    }
}

// ---------------- ball query via grid bins: warp per center, coalesced float4 ----------------
// Candidates streamed with one LDG.128 each (coords + orig idx). Predicate is
// bit-identical rn arithmetic; output = 32 smallest valid original indices
// ascending (bitonic sort), padded with the smallest — exact reference match.
__global__ void __launch_bounds__(256) ballq_kernel() {
    __shared__ int cand[8][64];

    const int w    = threadIdx.x >> 5;
    const int lane = threadIdx.x & 31;
    const int g    = blockIdx.x * 8 + w;       // 0..8191
    const int b    = g >> 10;
    const float4* XB = g_xyzBin + (size_t)b * NPTS;
    const int* CS  = g_cellStart + b * (NCELL + 1);

    const float cx = g_cent[(size_t)g * 3 + 0];
    const float cy = g_cent[(size_t)g * 3 + 1];
    const float cz = g_cent[(size_t)g * 3 + 2];
    int* out = g_gidx + (size_t)g * NSAMPLE;

    const float R2 = (float)(0.1 * 0.1);

    int icx = (int)(cx * 9.99f);
    int icy = (int)(cy * 9.99f);
    int icz = (int)(cz * 9.99f);
    int x0 = max(icx - 1, 0), x1 = min(icx + 1, 9);
    int y0 = max(icy - 1, 0), y1 = min(icy + 1, 9);
    int z0 = max(icz - 1, 0), z1 = min(icz + 1, 9);

    int cnt = 0;
    for (int sx = x0; sx <= x1; sx++) {
        for (int sy = y0; sy <= y1; sy++) {
            int cb = (sx * 10 + sy) * 10;
            int j0 = CS[cb + z0];
            int j1 = CS[cb + z1 + 1];               // z-range is contiguous
            for (int jj = j0; jj < j1; jj += 32) {
                int j = jj + lane;
                bool valid = false;
                int idx = 0;
                if (j < j1) {
                    float4 p = XB[j];               // coalesced LDG.128
                    idx = __float_as_int(p.w);
                    float dx = __fsub_rn(cx, p.x);
                    float dy = __fsub_rn(cy, p.y);
                    float dz = __fsub_rn(cz, p.z);
                    float d2 = __fadd_rn(__fadd_rn(__fmul_rn(dx, dx), __fmul_rn(dy, dy)),
                                         __fmul_rn(dz, dz));
                    valid = d2 < R2;
                }
                unsigned m = __ballot_sync(0xffffffffu, valid);
                if (valid) {
                    int pos = cnt + __popc(m & ((1u << lane) - 1u));
                    if (pos < 64) cand[w][pos] = idx;
                }
                cnt += __popc(m);
            }
        }
    }
    __syncwarp();

    int mcnt = cnt < 64 ? cnt : 64;
    int ca = (2 * lane     < mcnt) ? cand[w][2 * lane]     : SENT;
    int cb = (2 * lane + 1 < mcnt) ? cand[w][2 * lane + 1] : SENT;

    // bitonic sort of 64 ints, 2 per lane (element e = 2*lane + r), ascending
#pragma unroll
    for (int k = 2; k <= 64; k <<= 1) {
#pragma unroll
        for (int j = k >> 1; j >= 2; j >>= 1) {
            int jl = j >> 1;
            int pa = __shfl_xor_sync(0xffffffffu, ca, jl);
            int pb = __shfl_xor_sync(0xffffffffu, cb, jl);
            bool up = (((2 * lane) & k) == 0);
            bool lower = ((lane & jl) == 0);
            bool kmin = (up == lower);
            ca = kmin ? min(ca, pa) : max(ca, pa);
            cb = kmin ? min(cb, pb) : max(cb, pb);
        }
        {   // j == 1: intra-lane pair
            bool up = (((2 * lane) & k) == 0);
            int lo = min(ca, cb), hi = max(ca, cb);
            ca = up ? lo : hi;
            cb = up ? hi : lo;
        }
    }

    int first = __shfl_sync(0xffffffffu, ca, 0);   // smallest valid index (cnt>=1 always)
    if (lane < 16) {
        int v0 = (ca == SENT) ? first : ca;
        int v1 = (cb == SENT) ? first : cb;
        out[2 * lane + 0] = v0;
        out[2 * lane + 1] = v1;
    }
}

// ---------------- per-point feature GEMM: P = relu(bn(feat)) @ Wfeat^T ----------------
__global__ void __launch_bounds__(256) gemmP_kernel(const float* __restrict__ feat,
                                                    const float* __restrict__ bn_mean,
                                                    const float* __restrict__ bn_beta) {
    __shared__ float As[16][68];
    __shared__ float Bs[16][68];

    const int bm = blockIdx.x * 64;
    const int bn = blockIdx.y * 64;
    const int tid = threadIdx.x;

    const int row = tid >> 4;
    const int col = tid & 15;
    const int lm  = tid >> 2;
    const int lk4 = (tid & 3) * 4;
    const int kb  = tid >> 4;
    const int nb4 = (tid & 15) * 4;

    float acc[4][4];
#pragma unroll
    for (int i = 0; i < 4; i++)
#pragma unroll
        for (int j = 0; j < 4; j++) acc[i][j] = 0.f;

    for (int k0 = 0; k0 < CFEAT; k0 += 16) {
        float4 a4 = *(const float4*)(feat + (size_t)(bm + lm) * CFEAT + k0 + lk4);
        float av[4] = {a4.x, a4.y, a4.z, a4.w};
#pragma unroll
        for (int i = 0; i < 4; i++) {
            int c = k0 + lk4 + i + 3;
            float v = (av[i] - bn_mean[c]) * g_scale[c] + bn_beta[c];
            As[lk4 + i][lm] = fmaxf(v, 0.f);
        }
        float4 b4 = *(const float4*)(g_Wt + (size_t)(k0 + kb + 3) * COUT + bn + nb4);
        *(float4*)&Bs[kb][nb4] = b4;
        __syncthreads();

#pragma unroll
        for (int k = 0; k < 16; k++) {
            float4 a = *(float4*)&As[k][row * 4];
            float4 bq = *(float4*)&Bs[k][col * 4];
            float ar[4] = {a.x, a.y, a.z, a.w};
            float br[4] = {bq.x, bq.y, bq.z, bq.w};
#pragma unroll
            for (int i = 0; i < 4; i++)
#pragma unroll
                for (int j = 0; j < 4; j++) acc[i][j] += ar[i] * br[j];
        }
        __syncthreads();
    }

#pragma unroll
    for (int i = 0; i < 4; i++) {
        float4 o4 = make_float4(acc[i][0], acc[i][1], acc[i][2], acc[i][3]);
        *(float4*)(g_P + (size_t)(bm + row * 4 + i) * COUT + bn + col * 4) = o4;
    }
}

// ---------------- combine: gather P + xyz part, max over samples, bias, transpose ----------------
__global__ void __launch_bounds__(256) combine_kernel(const float* __restrict__ xyz,
                                                      const float* __restrict__ bias,
                                                      const float* __restrict__ bn_mean,
                                                      const float* __restrict__ bn_beta,
                                                      float* __restrict__ out_feat) {
    const int g = blockIdx.x;          // 0..8191
    const int b = g >> 10;
    const int s = g & 1023;
    const int o = threadIdx.x;         // 0..255

    __shared__ float t0[NSAMPLE], t1[NSAMPLE], t2[NSAMPLE];
    __shared__ int sidx[NSAMPLE];

    if (o < NSAMPLE) {
        int id = g_gidx[(size_t)g * NSAMPLE + o];
        sidx[o] = id;
        const float* Xp = xyz + ((size_t)b * NPTS + id) * 3;
        float cx = g_cent[(size_t)g * 3 + 0];
        float cy = g_cent[(size_t)g * 3 + 1];
        float cz = g_cent[(size_t)g * 3 + 2];
        float gx = __fsub_rn(Xp[0], cx);
        float gy = __fsub_rn(Xp[1], cy);
        float gz = __fsub_rn(Xp[2], cz);
        t0[o] = fmaxf((gx - bn_mean[0]) * g_scale[0] + bn_beta[0], 0.f);
        t1[o] = fmaxf((gy - bn_mean[1]) * g_scale[1] + bn_beta[1], 0.f);
        t2[o] = fmaxf((gz - bn_mean[2]) * g_scale[2] + bn_beta[2], 0.f);
    }
    __syncthreads();

    const float w0 = g_Wt[0 * COUT + o];
    const float w1 = g_Wt[1 * COUT + o];
    const float w2 = g_Wt[2 * COUT + o];
    const float* Pb = g_P + (size_t)b * NPTS * COUT;

    float acc = -3.402823466e+38f;
#pragma unroll 8
    for (int k = 0; k < NSAMPLE; k++) {
        float v = Pb[(size_t)sidx[k] * COUT + o];
        v = fmaf(w0, t0[k], v);
        v = fmaf(w1, t1[k], v);
        v = fmaf(w2, t2[k], v);
        acc = fmaxf(acc, v);
    }
    out_feat[((size_t)b * COUT + o) * NPOINT + s] = acc + bias[o];
}

// ---------------- launch: side stream runs bin + gemmP under FPS ----------------
extern "C" void kernel_launch(void* const* d_in, const int* in_sizes, int n_in,
                              void* d_out, int out_size) {
    const float* xyz   = (const float*)d_in[0];
    const float* feat  = (const float*)d_in[1];
    const float* W     = (const float*)d_in[2];
    const float* bias  = (const float*)d_in[3];
    const float* gamma = (const float*)d_in[4];
    const float* beta  = (const float*)d_in[5];
    const float* mean  = (const float*)d_in[6];
    const float* var   = (const float*)d_in[7];

    float* out = (float*)d_out;
    float* out_feat = out + ((size_t)out_size - (size_t)BATCH * COUT * NPOINT);

    cudaStream_t side;
    cudaEvent_t evFork, evBin, evJoin;
    cudaStreamCreateWithFlags(&side, cudaStreamNonBlocking);
    cudaEventCreateWithFlags(&evFork, cudaEventDisableTiming);
    cudaEventCreateWithFlags(&evBin, cudaEventDisableTiming);
    cudaEventCreateWithFlags(&evJoin, cudaEventDisableTiming);

    init_kernel<<<(CIN * COUT + 255) / 256, 256>>>(W, gamma, var);

    // fork: side branch = binning then gemmP (both independent of FPS, hidden under it)
    cudaEventRecord(evFork, 0);
    cudaStreamWaitEvent(side, evFork, 0);
    bin_kernel<<<BATCH, 1024, 0, side>>>(xyz);
    cudaEventRecord(evBin, side);
    gemmP_kernel<<<dim3((BATCH * NPTS) / 64, COUT / 64), 256, 0, side>>>(feat, mean, beta);
    cudaEventRecord(evJoin, side);

    // main branch: fps -> (wait bins) ballq
    fps_kernel<<<BATCH, 128>>>(xyz, out);
    cudaStreamWaitEvent(0, evBin, 0);
    ballq_kernel<<<BATCH * NPOINT / 8, 256>>>();

    // join: combine needs gemmP + ballq
    cudaStreamWaitEvent(0, evJoin, 0);
    combine_kernel<<<BATCH * NPOINT, 256>>>(xyz, bias, mean, beta, out_feat);
}